// round 14
// baseline (speedup 1.0000x reference)
#include <cuda_runtime.h>
#include <cuda_fp16.h>
#include <cstdint>

// Problem constants
#define T_   4096
#define H_   2048
#define I_   2816
#define E_   8
#define K_   2
#define TK_  (T_ * K_)

#define BK_      64          // k per mainloop iter (fp16) = 128B row
#define STAGES   3
#define STAGE_B  32768       // gemm13: A16K+G8K+U8K ; gemm2: A16K+B16K

#define N4X   (T_ * H_ / 4)
#define N413  (E_ * 2 * I_ * H_ / 4)
#define N413E (2 * I_ * H_ / 4)           // per-expert w13 float4 count
#define N42   (E_ * H_ * I_ / 4)

#define NCONV 96                          // converter CTAs in gemm13's z=0 slab

// ---------------- scratch (device globals; no allocs allowed) ----------------
__device__ int    g_counts[E_];
__device__ int    g_offsets[E_];
__device__ int    g_rowmap[TK_];                       // grouped pos -> flat slot (t*K+k)
__device__ int    g_done[2 + E_];                      // [0] route, [1] x, [2+e] w13[e]
__device__ __half g_xh  [(size_t)T_ * H_];             // x in fp16
__device__ __half g_w13h[(size_t)E_ * 2 * I_ * H_];    // w13 in fp16
__device__ __half g_w2h [(size_t)E_ * H_ * I_];        // w2 in fp16
__device__ __half g_act [(size_t)TK_ * I_];            // silu(gate)*up, grouped rows, fp16
__device__ __half g_ybuf[(size_t)TK_ * H_];            // per-slot weighted y (fp16)

// ---------------- helpers ----------------
__device__ __forceinline__ int load_id(const void* ids, int i, int is32) {
    return is32 ? ((const int*)ids)[i] : (int)((const long long*)ids)[i];
}

__device__ __forceinline__ void cvt4(const float4* s, uint2* d, int i) {
    float4 v = s[i];
    __half2 h0 = __floats2half2_rn(v.x, v.y);
    __half2 h1 = __floats2half2_rn(v.z, v.w);
    d[i] = make_uint2(*reinterpret_cast<uint32_t*>(&h0),
                      *reinterpret_cast<uint32_t*>(&h1));
}

// ---------------- reset flags (must run each call; graph replays reuse globals) ----
__global__ void k_reset() {
    if (threadIdx.x < 2 + E_) g_done[threadIdx.x] = 0;
}

// ---------------- mma / cp.async / ldmatrix helpers ----------------
__device__ __forceinline__ void mma16(float* d, const uint32_t* a, const uint32_t* b) {
    asm volatile(
        "mma.sync.aligned.m16n8k16.row.col.f32.f16.f16.f32 "
        "{%0,%1,%2,%3}, {%4,%5,%6,%7}, {%8,%9}, {%0,%1,%2,%3};"
        : "+f"(d[0]), "+f"(d[1]), "+f"(d[2]), "+f"(d[3])
        : "r"(a[0]), "r"(a[1]), "r"(a[2]), "r"(a[3]), "r"(b[0]), "r"(b[1]));
}
__device__ __forceinline__ void cpa16(uint32_t smem_dst, const void* gsrc) {
    asm volatile("cp.async.cg.shared.global [%0], [%1], 16;"
                 :: "r"(smem_dst), "l"(gsrc) : "memory");
}
__device__ __forceinline__ void cpa_commit() {
    asm volatile("cp.async.commit_group;" ::: "memory");
}
template <int N>
__device__ __forceinline__ void cpa_wait() {
    asm volatile("cp.async.wait_group %0;" :: "n"(N) : "memory");
}
__device__ __forceinline__ void ldsm4(uint32_t* r, uint32_t addr) {
    asm volatile("ldmatrix.sync.aligned.m8n8.x4.shared.b16 {%0,%1,%2,%3}, [%4];"
                 : "=r"(r[0]), "=r"(r[1]), "=r"(r[2]), "=r"(r[3]) : "r"(addr));
}

// byte offset of 16B chunk (r, ch) in a 128B-row tile, SW128 swizzle (ch ^= r&7)
__device__ __forceinline__ int chunk_off(int r, int ch) {
    return r * 128 + (((ch ^ (r & 7)) & 7) << 4);
}

// spin until counter reaches target (tid 0 only; caller syncs)
__device__ __forceinline__ void spin_on(int* p, int target) {
    while (atomicAdd(p, 0) < target) __nanosleep(512);
    __threadfence();
}

// ======================= GEMM13 (z=0: route + convert slab; z=1..8: experts) ========
// BM=128, BN=64 (g and u), BK=64. 256 thr, 8 warps as 4m x 2n, warp tile 32x32 (x2 g/u).
// smem/stage: A 16KB @0, G 8KB @16384, U 8KB @24576.  3 stages, 2 CTAs/SM.
__global__ __launch_bounds__(256, 2)
void k_gemm13(const void* __restrict__ ids,
              const float4* __restrict__ xsrc,
              const float4* __restrict__ w13src,
              const float4* __restrict__ w2src) {
    const int tid = threadIdx.x;

    // ---------------- z == 0: routing + conversion slab ----------------
    if (blockIdx.z == 0) {
        const int bid = blockIdx.y * gridDim.x + blockIdx.x;
        if (bid == 0) {
            // routing (one CTA)
            __shared__ int s_cnt[E_], s_cur[E_], s_off[E_];
            __shared__ int s_is32;
            if (tid == 0) s_is32 = 0;
            if (tid < E_) { s_cnt[tid] = 0; s_cur[tid] = 0; }
            __syncthreads();
            const int* idsv = (const int*)ids;
            int any = 0;
            for (int i = tid * 2 + 1; i < TK_; i += 512) any |= idsv[i];
            if (any) atomicOr(&s_is32, 1);
            __syncthreads();
            const int is32 = s_is32;
            for (int i = tid; i < TK_; i += 256)
                atomicAdd(&s_cnt[load_id(ids, i, is32)], 1);
            __syncthreads();
            if (tid == 0) {
                int acc = 0;
                for (int e = 0; e < E_; e++) { s_off[e] = acc; acc += s_cnt[e]; }
            }
            __syncthreads();
            for (int i = tid; i < TK_; i += 256) {
                int e = load_id(ids, i, is32);
                int pos = s_off[e] + atomicAdd(&s_cur[e], 1);
                g_rowmap[pos] = i;
            }
            if (tid < E_) { g_counts[tid] = s_cnt[tid]; g_offsets[tid] = s_off[tid]; }
            __threadfence();
            __syncthreads();
            if (tid == 0) atomicAdd(&g_done[0], 1);
            return;
        }
        if (bid > NCONV) return;
        const int c = bid - 1;                         // 0..NCONV-1
        const long long start  = (long long)c * 256 + tid;
        const long long stride = (long long)NCONV * 256;
        // x
        for (long long i = start; i < N4X; i += stride)
            cvt4(xsrc, (uint2*)g_xh, (int)i);
        __threadfence();
        __syncthreads();
        if (tid == 0) atomicAdd(&g_done[1], 1);
        // w13, expert by expert (progressive unlock)
        for (int e = 0; e < E_; e++) {
            const long long base = (long long)e * N413E;
            for (long long i = start; i < N413E; i += stride)
                cvt4(w13src, (uint2*)g_w13h, (int)(base + i));
            __threadfence();
            __syncthreads();
            if (tid == 0) atomicAdd(&g_done[2 + e], 1);
        }
        // w2 (kernel boundary orders it before gemm2)
        for (long long i = start; i < N42; i += stride)
            cvt4(w2src, (uint2*)g_w2h, (int)i);
        return;
    }

    // ---------------- z >= 1: GEMM expert e = z-1 ----------------
    extern __shared__ uint32_t sm[];
    const int e = blockIdx.z - 1;

    // wait for routing
    if (tid == 0) spin_on(&g_done[0], 1);
    __syncthreads();

    const int cnt = g_counts[e];
    const int m0  = blockIdx.y * 128;
    if (m0 >= cnt) return;
    const int off = g_offsets[e];
    const int n0  = blockIdx.x * 64;

    const uint32_t sb = (uint32_t)__cvta_generic_to_shared(sm);
    const int warp = tid >> 5, lane = tid & 31;
    const int wm = (warp >> 1) * 32;          // 0,32,64,96
    const int wn = (warp & 1) * 32;           // 0,32
    const int row0 = lane >> 2, c0 = lane & 3;
    const int lrow = lane & 15, lch = lane >> 4;

    // ---- producer mappings ----
    const __half* aS[4]; int sAo[4];
    #pragma unroll
    for (int j = 0; j < 4; j++) {
        int f = tid + j * 256, r = f >> 3, ch = f & 7;
        sAo[j] = chunk_off(r, ch);
        int pos = m0 + r;
        int idx = (pos < cnt) ? (off + pos) : off;
        int tok = g_rowmap[idx] >> 1;          // K_=2
        aS[j] = g_xh + (size_t)tok * H_ + ch * 8;
    }
    const __half* gS[2]; const __half* uS[2]; int sGo[2], sUo[2];
    #pragma unroll
    for (int j = 0; j < 2; j++) {
        int f = tid + j * 256, r = f >> 3, ch = f & 7;
        sGo[j] = 16384 + chunk_off(r, ch);
        sUo[j] = 24576 + chunk_off(r, ch);
        gS[j] = g_w13h + (size_t)e * (2 * I_) * H_ + (size_t)(n0 + r) * H_ + ch * 8;
        uS[j] = gS[j] + (size_t)I_ * H_;
    }

    // ---- consumer ldmatrix lane offsets, ks = 0..3 ----
    int offA[2][4], offG[2][4], offU[2][4];
    #pragma unroll
    for (int ks = 0; ks < 4; ks++) {
        #pragma unroll
        for (int q = 0; q < 2; q++) {
            offA[q][ks] = chunk_off(wm + q * 16 + lrow, 2 * ks + lch);
            offG[q][ks] = 16384 + chunk_off(wn + q * 16 + lrow, 2 * ks + lch);
            offU[q][ks] = 24576 + chunk_off(wn + q * 16 + lrow, 2 * ks + lch);
        }
    }

    // wait for converted inputs (x + this expert's w13)
    if (tid == 0) {
        spin_on(&g_done[1], NCONV);
        spin_on(&g_done[2 + e], NCONV);
    }
    __syncthreads();

    const int KT = H_ / BK_;                   // 32 = 3*10 + 2
    auto issue = [&](int kt, int st) {
        const int kk = kt * BK_;
        const uint32_t base = sb + st * STAGE_B;
        #pragma unroll
        for (int j = 0; j < 4; j++) cpa16(base + sAo[j], aS[j] + kk);
        #pragma unroll
        for (int j = 0; j < 2; j++) {
            cpa16(base + sGo[j], gS[j] + kk);
            cpa16(base + sUo[j], uS[j] + kk);
        }
    };

    float gacc[2][4][4], uacc[2][4][4];
    #pragma unroll
    for (int a = 0; a < 2; a++)
        #pragma unroll
        for (int b = 0; b < 4; b++)
            #pragma unroll
            for (int c = 0; c < 4; c++) { gacc[a][b][c] = 0.f; uacc[a][b][c] = 0.f; }

    issue(0, 0); cpa_commit();
    issue(1, 1); cpa_commit();

    // step body: wait -> sync -> issue(kt+2, stage (s+2)%3) -> commit -> compute(stage s)
    auto step = [&](int kt, int s) {
        cpa_wait<STAGES - 2>();
        __syncthreads();
        if (kt + 2 < KT) issue(kt + 2, (s + 2) % 3);
        cpa_commit();
        const uint32_t base = sb + s * STAGE_B;
        #pragma unroll
        for (int ks = 0; ks < 4; ks++) {
            uint32_t a0[4], a1[4];
            ldsm4(a0, base + offA[0][ks]);
            ldsm4(a1, base + offA[1][ks]);
            uint32_t gp0[4], gp1[4], up0[4], up1[4];
            ldsm4(gp0, base + offG[0][ks]);
            ldsm4(gp1, base + offG[1][ks]);
            ldsm4(up0, base + offU[0][ks]);
            ldsm4(up1, base + offU[1][ks]);
            #pragma unroll
            for (int p = 0; p < 2; p++) {
                const uint32_t* gp = p ? gp1 : gp0;
                const uint32_t* up = p ? up1 : up0;
                #pragma unroll
                for (int sub = 0; sub < 2; sub++) {
                    uint32_t bg[2] = { gp[sub], gp[sub + 2] };
                    uint32_t bu[2] = { up[sub], up[sub + 2] };
                    const int nf = 2 * p + sub;
                    mma16(gacc[0][nf], a0, bg);
                    mma16(gacc[1][nf], a1, bg);
                    mma16(uacc[0][nf], a0, bu);
                    mma16(uacc[1][nf], a1, bu);
                }
            }
        }
    };

    for (int kt0 = 0; kt0 < 30; kt0 += 3) {
        #pragma unroll
        for (int s = 0; s < 3; s++) step(kt0 + s, s);
    }
    step(30, 0);
    step(31, 1);

    // Epilogue: act = silu(gate) * up -> g_act (fp16)
    const int rows_left = cnt - m0;
    #pragma unroll
    for (int mf = 0; mf < 2; mf++) {
        #pragma unroll
        for (int half = 0; half < 2; half++) {
            int r = wm + mf * 16 + row0 + half * 8;
            if (r < rows_left) {
                size_t base = (size_t)(off + m0 + r) * I_ + n0 + wn;
                #pragma unroll
                for (int nf = 0; nf < 4; nf++) {
                    float g0 = gacc[mf][nf][half * 2 + 0];
                    float g1 = gacc[mf][nf][half * 2 + 1];
                    float u0 = uacc[mf][nf][half * 2 + 0];
                    float u1 = uacc[mf][nf][half * 2 + 1];
                    float a0 = g0 / (1.f + __expf(-g0)) * u0;
                    float a1 = g1 / (1.f + __expf(-g1)) * u1;
                    int c = nf * 8 + c0 * 2;
                    *reinterpret_cast<__half2*>(g_act + base + c) = __floats2half2_rn(a0, a1);
                }
            }
        }
    }
}

// ======================= GEMM2: ybuf[slot] = tw[slot] * (act @ w2^T) =================
// BM=128, BN=128, BK=64. 8 warps as 2m x 4n, warp tile 64x32. smem/stage: A 16K + B 16K.
__global__ __launch_bounds__(256, 2)
void k_gemm2(const float* __restrict__ tw) {
    extern __shared__ uint32_t sm[];
    const int e   = blockIdx.z;
    const int cnt = g_counts[e];
    const int m0  = blockIdx.y * 128;
    if (m0 >= cnt) return;
    const int off = g_offsets[e];
    const int n0  = blockIdx.x * 128;

    const uint32_t sb = (uint32_t)__cvta_generic_to_shared(sm);
    const int tid  = threadIdx.x;
    const int warp = tid >> 5, lane = tid & 31;
    const int wm = (warp >> 2) * 64;          // 0,64
    const int wn = (warp & 3) * 32;           // 0..96
    const int row0 = lane >> 2, c0 = lane & 3;
    const int lrow = lane & 15, lch = lane >> 4;

    // ---- producers: A and B each 128 rows x 8 chunks -> 4 per thread ----
    const __half* aS[4]; int sAo[4];
    const __half* bS[4]; int sBo[4];
    #pragma unroll
    for (int j = 0; j < 4; j++) {
        int f = tid + j * 256, r = f >> 3, ch = f & 7;
        sAo[j] = chunk_off(r, ch);
        sBo[j] = 16384 + chunk_off(r, ch);
        int pos = m0 + r;
        int row = (pos < cnt) ? (off + pos) : off;
        aS[j] = g_act + (size_t)row * I_ + ch * 8;
        bS[j] = g_w2h + (size_t)e * H_ * I_ + (size_t)(n0 + r) * I_ + ch * 8;
    }

    // ---- ldmatrix lane offsets ----
    int offA[4][4], offB[2][4];
    #pragma unroll
    for (int ks = 0; ks < 4; ks++) {
        #pragma unroll
        for (int mf = 0; mf < 4; mf++)
            offA[mf][ks] = chunk_off(wm + mf * 16 + lrow, 2 * ks + lch);
        #pragma unroll
        for (int p = 0; p < 2; p++)
            offB[p][ks] = 16384 + chunk_off(wn + p * 16 + lrow, 2 * ks + lch);
    }

    const int KT = I_ / BK_;                   // 44 = 3*14 + 2
    auto issue = [&](int kt, int st) {
        const int kk = kt * BK_;
        const uint32_t base = sb + st * STAGE_B;
        #pragma unroll
        for (int j = 0; j < 4; j++) {
            cpa16(base + sAo[j], aS[j] + kk);
            cpa16(base + sBo[j], bS[j] + kk);
        }
    };

    float acc[4][4][4];
    #pragma unroll
    for (int a = 0; a < 4; a++)
        #pragma unroll
        for (int b = 0; b < 4; b++)
            #pragma unroll
            for (int c = 0; c < 4; c++) acc[a][b][c] = 0.f;

    issue(0, 0); cpa_commit();
    issue(1, 1); cpa_commit();

    auto step = [&](int kt, int s) {
        cpa_wait<STAGES - 2>();
        __syncthreads();
        if (kt + 2 < KT) issue(kt + 2, (s + 2) % 3);
        cpa_commit();
        const uint32_t base = sb + s * STAGE_B;
        #pragma unroll
        for (int ks = 0; ks < 4; ks++) {
            uint32_t af[4][4];
            #pragma unroll
            for (int mf = 0; mf < 4; mf++) ldsm4(af[mf], base + offA[mf][ks]);
            uint32_t bp0[4], bp1[4];
            ldsm4(bp0, base + offB[0][ks]);
            ldsm4(bp1, base + offB[1][ks]);
            #pragma unroll
            for (int p = 0; p < 2; p++) {
                const uint32_t* bp = p ? bp1 : bp0;
                #pragma unroll
                for (int sub = 0; sub < 2; sub++) {
                    uint32_t bf[2] = { bp[sub], bp[sub + 2] };
                    const int nf = 2 * p + sub;
                    #pragma unroll
                    for (int mf = 0; mf < 4; mf++) mma16(acc[mf][nf], af[mf], bf);
                }
            }
        }
    };

    for (int kt0 = 0; kt0 < 42; kt0 += 3) {
        #pragma unroll
        for (int s = 0; s < 3; s++) step(kt0 + s, s);
    }
    step(42, 0);
    step(43, 1);

    const int rows_left = cnt - m0;
    #pragma unroll
    for (int mf = 0; mf < 4; mf++) {
        #pragma unroll
        for (int half = 0; half < 2; half++) {
            int r = wm + mf * 16 + row0 + half * 8;
            if (r < rows_left) {
                int slot = g_rowmap[off + m0 + r];
                float w = tw[slot];
                size_t base = (size_t)slot * H_ + n0 + wn;
                #pragma unroll
                for (int nf = 0; nf < 4; nf++) {
                    float y0 = acc[mf][nf][half * 2 + 0] * w;
                    float y1 = acc[mf][nf][half * 2 + 1] * w;
                    int c = nf * 8 + c0 * 2;
                    *reinterpret_cast<__half2*>(g_ybuf + base + c) = __floats2half2_rn(y0, y1);
                }
            }
        }
    }
}

// ---------------- combine: out[t] = ybuf[2t] + ybuf[2t+1] (fp16 in, fp32 out) -------
__global__ void k_combine(float* __restrict__ out) {
    int i = blockIdx.x * blockDim.x + threadIdx.x;     // over T_*H_/8
    const int HW8 = H_ / 8;
    if (i < T_ * HW8) {
        int t = i / HW8, h8 = i % HW8;
        const uint4* yb = reinterpret_cast<const uint4*>(g_ybuf);
        uint4 a = yb[(size_t)(2 * t) * HW8 + h8];
        uint4 b = yb[(size_t)(2 * t + 1) * HW8 + h8];
        float4 o0, o1;
        {
            float2 p = __half22float2(*reinterpret_cast<__half2*>(&a.x));
            float2 q = __half22float2(*reinterpret_cast<__half2*>(&b.x));
            o0.x = p.x + q.x; o0.y = p.y + q.y;
            p = __half22float2(*reinterpret_cast<__half2*>(&a.y));
            q = __half22float2(*reinterpret_cast<__half2*>(&b.y));
            o0.z = p.x + q.x; o0.w = p.y + q.y;
            p = __half22float2(*reinterpret_cast<__half2*>(&a.z));
            q = __half22float2(*reinterpret_cast<__half2*>(&b.z));
            o1.x = p.x + q.x; o1.y = p.y + q.y;
            p = __half22float2(*reinterpret_cast<__half2*>(&a.w));
            q = __half22float2(*reinterpret_cast<__half2*>(&b.w));
            o1.z = p.x + q.x; o1.w = p.y + q.y;
        }
        float4* op = reinterpret_cast<float4*>(out + (size_t)t * H_ + h8 * 8);
        op[0] = o0; op[1] = o1;
    }
}

// ---------------- launch ----------------
extern "C" void kernel_launch(void* const* d_in, const int* in_sizes, int n_in,
                              void* d_out, int out_size) {
    const float* x   = (const float*)d_in[0];
    const float* w13 = (const float*)d_in[1];
    const float* w2  = (const float*)d_in[2];
    const float* tw  = (const float*)d_in[3];
    const void*  ids = d_in[4];
    float* out = (float*)d_out;

    const int smem = STAGES * STAGE_B;        // 98304 B per CTA
    cudaFuncSetAttribute(k_gemm13, cudaFuncAttributeMaxDynamicSharedMemorySize, smem);
    cudaFuncSetAttribute(k_gemm2,  cudaFuncAttributeMaxDynamicSharedMemorySize, smem);

    // idx 0: reset producer/consumer flags (graph replays reuse device globals)
    k_reset<<<1, 32>>>();
    // idx 1: fused routing + fp16 conversion (z=0 slab) + gemm13 (z=1..8)
    dim3 g13(I_ / 64, TK_ / 128, E_ + 1);     // (44, 64, 9)
    k_gemm13<<<g13, 256, smem>>>(ids, (const float4*)x,
                                 (const float4*)w13, (const float4*)w2);
    // idx 2: gemm2 (w2h finished inside idx 1; kernel boundary orders it)
    dim3 g2(H_ / 128, TK_ / 128, E_);         // (16, 64, 8)
    k_gemm2<<<g2, 256, smem>>>(tw);
    // idx 3: combine
    k_combine<<<(T_ * (H_ / 8) + 255) / 256, 256>>>(out);
}

// round 15
// speedup vs baseline: 1.2331x; 1.2331x over previous
#include <cuda_runtime.h>
#include <cuda_fp16.h>
#include <cstdint>

// Problem constants
#define T_   4096
#define H_   2048
#define I_   2816
#define E_   8
#define K_   2
#define TK_  (T_ * K_)

#define BK_      64          // k per mainloop iter (fp16) = 128B row
#define STAGES   3
#define STAGE_B  32768       // gemm13: A16K+G8K+U8K ; gemm2: A16K+B16K

#define N4X  (T_ * H_ / 4)
#define N413 (E_ * 2 * I_ * H_ / 4)
#define N42  (E_ * H_ * I_ / 4)

// ---------------- scratch (device globals; no allocs allowed) ----------------
__device__ int    g_counts[E_];
__device__ int    g_offsets[E_];
__device__ int    g_rowmap[TK_];                       // grouped pos -> flat slot (t*K+k)
__device__ __half g_xh  [(size_t)T_ * H_];             // x in fp16
__device__ __half g_w13h[(size_t)E_ * 2 * I_ * H_];    // w13 in fp16
__device__ __half g_w2h [(size_t)E_ * H_ * I_];        // w2 in fp16
__device__ __half g_act [(size_t)TK_ * I_];            // silu(gate)*up, grouped rows, fp16
__device__ __half g_ybuf[(size_t)TK_ * H_];            // per-slot weighted y (fp16)

// ---------------- helpers ----------------
__device__ __forceinline__ int load_id(const void* ids, int i, int is32) {
    return is32 ? ((const int*)ids)[i] : (int)((const long long*)ids)[i];
}

__device__ __forceinline__ void cvt4(const float4* s, uint2* d, int i) {
    float4 v = s[i];
    __half2 h0 = __floats2half2_rn(v.x, v.y);
    __half2 h1 = __floats2half2_rn(v.z, v.w);
    d[i] = make_uint2(*reinterpret_cast<uint32_t*>(&h0),
                      *reinterpret_cast<uint32_t*>(&h1));
}

// ---------------- prep: block 0 routes; other blocks convert x + w13 (MLP=2) -------
__global__ void k_prep(const void* __restrict__ ids,
                       const float4* __restrict__ x,
                       const float4* __restrict__ w13) {
    const int tid = threadIdx.x;                       // 256 threads
    if (blockIdx.x == 0) {
        __shared__ int s_cnt[E_], s_cur[E_], s_off[E_];
        __shared__ int s_is32;
        if (tid == 0) s_is32 = 0;
        if (tid < E_) { s_cnt[tid] = 0; s_cur[tid] = 0; }
        __syncthreads();
        const int* idsv = (const int*)ids;
        int any = 0;
        for (int i = tid * 2 + 1; i < TK_; i += 512) any |= idsv[i];
        if (any) atomicOr(&s_is32, 1);
        __syncthreads();
        const int is32 = s_is32;
        for (int i = tid; i < TK_; i += 256)
            atomicAdd(&s_cnt[load_id(ids, i, is32)], 1);
        __syncthreads();
        if (tid == 0) {
            int acc = 0;
            for (int e = 0; e < E_; e++) { s_off[e] = acc; acc += s_cnt[e]; }
        }
        __syncthreads();
        for (int i = tid; i < TK_; i += 256) {
            int e = load_id(ids, i, is32);
            int pos = s_off[e] + atomicAdd(&s_cur[e], 1);
            g_rowmap[pos] = i;
        }
        if (tid < E_) { g_counts[tid] = s_cnt[tid]; g_offsets[tid] = s_off[tid]; }
    } else {
        // convert x fully + all of w13; 2 independent float4 per iteration (MLP=2)
        const long long total = (long long)N4X + N413;
        long long idx    = (long long)(blockIdx.x - 1) * 512 + tid;
        long long stride = (long long)(gridDim.x - 1) * 512;
        for (long long i = idx; i < total; i += stride) {
            long long i0 = i, i1 = i + 256;
            // i0
            if (i0 < N4X) cvt4(x, (uint2*)g_xh, (int)i0);
            else          cvt4(w13, (uint2*)g_w13h, (int)(i0 - N4X));
            // i1 (independent load, issued back-to-back by the compiler)
            if (i1 < total) {
                if (i1 < N4X) cvt4(x, (uint2*)g_xh, (int)i1);
                else          cvt4(w13, (uint2*)g_w13h, (int)(i1 - N4X));
            }
        }
    }
}

// ---------------- mma / cp.async / ldmatrix helpers ----------------
__device__ __forceinline__ void mma16(float* d, const uint32_t* a, const uint32_t* b) {
    asm volatile(
        "mma.sync.aligned.m16n8k16.row.col.f32.f16.f16.f32 "
        "{%0,%1,%2,%3}, {%4,%5,%6,%7}, {%8,%9}, {%0,%1,%2,%3};"
        : "+f"(d[0]), "+f"(d[1]), "+f"(d[2]), "+f"(d[3])
        : "r"(a[0]), "r"(a[1]), "r"(a[2]), "r"(a[3]), "r"(b[0]), "r"(b[1]));
}
__device__ __forceinline__ void cpa16(uint32_t smem_dst, const void* gsrc) {
    asm volatile("cp.async.cg.shared.global [%0], [%1], 16;"
                 :: "r"(smem_dst), "l"(gsrc) : "memory");
}
__device__ __forceinline__ void cpa_commit() {
    asm volatile("cp.async.commit_group;" ::: "memory");
}
template <int N>
__device__ __forceinline__ void cpa_wait() {
    asm volatile("cp.async.wait_group %0;" :: "n"(N) : "memory");
}
__device__ __forceinline__ void ldsm4(uint32_t* r, uint32_t addr) {
    asm volatile("ldmatrix.sync.aligned.m8n8.x4.shared.b16 {%0,%1,%2,%3}, [%4];"
                 : "=r"(r[0]), "=r"(r[1]), "=r"(r[2]), "=r"(r[3]) : "r"(addr));
}

// byte offset of 16B chunk (r, ch) in a 128B-row tile, SW128 swizzle (ch ^= r&7)
__device__ __forceinline__ int chunk_off(int r, int ch) {
    return r * 128 + (((ch ^ (r & 7)) & 7) << 4);
}

// ======================= GEMM13 (z=E_: w2 converter slice) ===========================
// BM=128, BN=64 (g and u), BK=64. 256 thr, 8 warps as 4m x 2n, warp tile 32x32 (x2 g/u).
// smem/stage: A 16KB @0, G 8KB @16384, U 8KB @24576.  3 stages, 2 CTAs/SM.
__global__ __launch_bounds__(256, 2)
void k_gemm13(const float4* __restrict__ w2src) {
    // --- co-scheduled slice: convert w2 fp32 -> fp16 while gemm13 runs ---
    if (blockIdx.z == E_) {
        int bid = blockIdx.y * gridDim.x + blockIdx.x;
        long long idx    = (long long)bid * 256 + threadIdx.x;
        long long stride = (long long)gridDim.x * gridDim.y * 256;
        for (long long i = idx; i < N42; i += stride)
            cvt4(w2src, (uint2*)g_w2h, (int)i);
        return;
    }

    extern __shared__ uint32_t sm[];
    const int e   = blockIdx.z;
    const int cnt = g_counts[e];
    const int m0  = blockIdx.y * 128;
    if (m0 >= cnt) return;
    const int off = g_offsets[e];
    const int n0  = blockIdx.x * 64;

    const uint32_t sb = (uint32_t)__cvta_generic_to_shared(sm);
    const int tid  = threadIdx.x;
    const int warp = tid >> 5, lane = tid & 31;
    const int wm = (warp >> 1) * 32;          // 0,32,64,96
    const int wn = (warp & 1) * 32;           // 0,32
    const int row0 = lane >> 2, c0 = lane & 3;
    const int lrow = lane & 15, lch = lane >> 4;

    // ---- producer mappings ----
    const __half* aS[4]; int sAo[4];
    #pragma unroll
    for (int j = 0; j < 4; j++) {
        int f = tid + j * 256, r = f >> 3, ch = f & 7;
        sAo[j] = chunk_off(r, ch);
        int pos = m0 + r;
        int idx = (pos < cnt) ? (off + pos) : off;
        int tok = g_rowmap[idx] >> 1;          // K_=2
        aS[j] = g_xh + (size_t)tok * H_ + ch * 8;
    }
    const __half* gS[2]; const __half* uS[2]; int sGo[2], sUo[2];
    #pragma unroll
    for (int j = 0; j < 2; j++) {
        int f = tid + j * 256, r = f >> 3, ch = f & 7;
        sGo[j] = 16384 + chunk_off(r, ch);
        sUo[j] = 24576 + chunk_off(r, ch);
        gS[j] = g_w13h + (size_t)e * (2 * I_) * H_ + (size_t)(n0 + r) * H_ + ch * 8;
        uS[j] = gS[j] + (size_t)I_ * H_;
    }

    // ---- consumer ldmatrix lane offsets, ks = 0..3 ----
    int offA[2][4], offG[2][4], offU[2][4];
    #pragma unroll
    for (int ks = 0; ks < 4; ks++) {
        #pragma unroll
        for (int q = 0; q < 2; q++) {
            offA[q][ks] = chunk_off(wm + q * 16 + lrow, 2 * ks + lch);
            offG[q][ks] = 16384 + chunk_off(wn + q * 16 + lrow, 2 * ks + lch);
            offU[q][ks] = 24576 + chunk_off(wn + q * 16 + lrow, 2 * ks + lch);
        }
    }

    const int KT = H_ / BK_;                   // 32 = 3*10 + 2
    auto issue = [&](int kt, int st) {
        const int kk = kt * BK_;
        const uint32_t base = sb + st * STAGE_B;
        #pragma unroll
        for (int j = 0; j < 4; j++) cpa16(base + sAo[j], aS[j] + kk);
        #pragma unroll
        for (int j = 0; j < 2; j++) {
            cpa16(base + sGo[j], gS[j] + kk);
            cpa16(base + sUo[j], uS[j] + kk);
        }
    };

    float gacc[2][4][4], uacc[2][4][4];
    #pragma unroll
    for (int a = 0; a < 2; a++)
        #pragma unroll
        for (int b = 0; b < 4; b++)
            #pragma unroll
            for (int c = 0; c < 4; c++) { gacc[a][b][c] = 0.f; uacc[a][b][c] = 0.f; }

    issue(0, 0); cpa_commit();
    issue(1, 1); cpa_commit();

    // step body: wait -> sync -> issue(kt+2, stage (s+2)%3) -> commit -> compute(stage s)
    auto step = [&](int kt, int s) {
        cpa_wait<STAGES - 2>();
        __syncthreads();
        if (kt + 2 < KT) issue(kt + 2, (s + 2) % 3);
        cpa_commit();
        const uint32_t base = sb + s * STAGE_B;
        #pragma unroll
        for (int ks = 0; ks < 4; ks++) {
            uint32_t a0[4], a1[4];
            ldsm4(a0, base + offA[0][ks]);
            ldsm4(a1, base + offA[1][ks]);
            uint32_t gp0[4], gp1[4], up0[4], up1[4];
            ldsm4(gp0, base + offG[0][ks]);
            ldsm4(gp1, base + offG[1][ks]);
            ldsm4(up0, base + offU[0][ks]);
            ldsm4(up1, base + offU[1][ks]);
            #pragma unroll
            for (int p = 0; p < 2; p++) {
                const uint32_t* gp = p ? gp1 : gp0;
                const uint32_t* up = p ? up1 : up0;
                #pragma unroll
                for (int sub = 0; sub < 2; sub++) {
                    uint32_t bg[2] = { gp[sub], gp[sub + 2] };
                    uint32_t bu[2] = { up[sub], up[sub + 2] };
                    const int nf = 2 * p + sub;
                    mma16(gacc[0][nf], a0, bg);
                    mma16(gacc[1][nf], a1, bg);
                    mma16(uacc[0][nf], a0, bu);
                    mma16(uacc[1][nf], a1, bu);
                }
            }
        }
    };

    for (int kt0 = 0; kt0 < 30; kt0 += 3) {
        #pragma unroll
        for (int s = 0; s < 3; s++) step(kt0 + s, s);
    }
    step(30, 0);
    step(31, 1);

    // Epilogue: act = silu(gate) * up -> g_act (fp16)
    const int rows_left = cnt - m0;
    #pragma unroll
    for (int mf = 0; mf < 2; mf++) {
        #pragma unroll
        for (int half = 0; half < 2; half++) {
            int r = wm + mf * 16 + row0 + half * 8;
            if (r < rows_left) {
                size_t base = (size_t)(off + m0 + r) * I_ + n0 + wn;
                #pragma unroll
                for (int nf = 0; nf < 4; nf++) {
                    float g0 = gacc[mf][nf][half * 2 + 0];
                    float g1 = gacc[mf][nf][half * 2 + 1];
                    float u0 = uacc[mf][nf][half * 2 + 0];
                    float u1 = uacc[mf][nf][half * 2 + 1];
                    float a0 = g0 / (1.f + __expf(-g0)) * u0;
                    float a1 = g1 / (1.f + __expf(-g1)) * u1;
                    int c = nf * 8 + c0 * 2;
                    *reinterpret_cast<__half2*>(g_act + base + c) = __floats2half2_rn(a0, a1);
                }
            }
        }
    }
}

// ======================= GEMM2: ybuf[slot] = tw[slot] * (act @ w2^T) =================
// BM=128, BN=128, BK=64. 8 warps as 2m x 4n, warp tile 64x32. smem/stage: A 16K + B 16K.
__global__ __launch_bounds__(256, 2)
void k_gemm2(const float* __restrict__ tw) {
    extern __shared__ uint32_t sm[];
    const int e   = blockIdx.z;
    const int cnt = g_counts[e];
    const int m0  = blockIdx.y * 128;
    if (m0 >= cnt) return;
    const int off = g_offsets[e];
    const int n0  = blockIdx.x * 128;

    const uint32_t sb = (uint32_t)__cvta_generic_to_shared(sm);
    const int tid  = threadIdx.x;
    const int warp = tid >> 5, lane = tid & 31;
    const int wm = (warp >> 2) * 64;          // 0,64
    const int wn = (warp & 3) * 32;           // 0..96
    const int row0 = lane >> 2, c0 = lane & 3;
    const int lrow = lane & 15, lch = lane >> 4;

    // ---- producers: A and B each 128 rows x 8 chunks -> 4 per thread ----
    const __half* aS[4]; int sAo[4];
    const __half* bS[4]; int sBo[4];
    #pragma unroll
    for (int j = 0; j < 4; j++) {
        int f = tid + j * 256, r = f >> 3, ch = f & 7;
        sAo[j] = chunk_off(r, ch);
        sBo[j] = 16384 + chunk_off(r, ch);
        int pos = m0 + r;
        int row = (pos < cnt) ? (off + pos) : off;
        aS[j] = g_act + (size_t)row * I_ + ch * 8;
        bS[j] = g_w2h + (size_t)e * H_ * I_ + (size_t)(n0 + r) * I_ + ch * 8;
    }

    // ---- ldmatrix lane offsets ----
    int offA[4][4], offB[2][4];
    #pragma unroll
    for (int ks = 0; ks < 4; ks++) {
        #pragma unroll
        for (int mf = 0; mf < 4; mf++)
            offA[mf][ks] = chunk_off(wm + mf * 16 + lrow, 2 * ks + lch);
        #pragma unroll
        for (int p = 0; p < 2; p++)
            offB[p][ks] = 16384 + chunk_off(wn + p * 16 + lrow, 2 * ks + lch);
    }

    const int KT = I_ / BK_;                   // 44 = 3*14 + 2
    auto issue = [&](int kt, int st) {
        const int kk = kt * BK_;
        const uint32_t base = sb + st * STAGE_B;
        #pragma unroll
        for (int j = 0; j < 4; j++) {
            cpa16(base + sAo[j], aS[j] + kk);
            cpa16(base + sBo[j], bS[j] + kk);
        }
    };

    float acc[4][4][4];
    #pragma unroll
    for (int a = 0; a < 4; a++)
        #pragma unroll
        for (int b = 0; b < 4; b++)
            #pragma unroll
            for (int c = 0; c < 4; c++) acc[a][b][c] = 0.f;

    issue(0, 0); cpa_commit();
    issue(1, 1); cpa_commit();

    auto step = [&](int kt, int s) {
        cpa_wait<STAGES - 2>();
        __syncthreads();
        if (kt + 2 < KT) issue(kt + 2, (s + 2) % 3);
        cpa_commit();
        const uint32_t base = sb + s * STAGE_B;
        #pragma unroll
        for (int ks = 0; ks < 4; ks++) {
            uint32_t af[4][4];
            #pragma unroll
            for (int mf = 0; mf < 4; mf++) ldsm4(af[mf], base + offA[mf][ks]);
            uint32_t bp0[4], bp1[4];
            ldsm4(bp0, base + offB[0][ks]);
            ldsm4(bp1, base + offB[1][ks]);
            #pragma unroll
            for (int p = 0; p < 2; p++) {
                const uint32_t* bp = p ? bp1 : bp0;
                #pragma unroll
                for (int sub = 0; sub < 2; sub++) {
                    uint32_t bf[2] = { bp[sub], bp[sub + 2] };
                    const int nf = 2 * p + sub;
                    #pragma unroll
                    for (int mf = 0; mf < 4; mf++) mma16(acc[mf][nf], af[mf], bf);
                }
            }
        }
    };

    for (int kt0 = 0; kt0 < 42; kt0 += 3) {
        #pragma unroll
        for (int s = 0; s < 3; s++) step(kt0 + s, s);
    }
    step(42, 0);
    step(43, 1);

    const int rows_left = cnt - m0;
    #pragma unroll
    for (int mf = 0; mf < 4; mf++) {
        #pragma unroll
        for (int half = 0; half < 2; half++) {
            int r = wm + mf * 16 + row0 + half * 8;
            if (r < rows_left) {
                int slot = g_rowmap[off + m0 + r];
                float w = tw[slot];
                size_t base = (size_t)slot * H_ + n0 + wn;
                #pragma unroll
                for (int nf = 0; nf < 4; nf++) {
                    float y0 = acc[mf][nf][half * 2 + 0] * w;
                    float y1 = acc[mf][nf][half * 2 + 1] * w;
                    int c = nf * 8 + c0 * 2;
                    *reinterpret_cast<__half2*>(g_ybuf + base + c) = __floats2half2_rn(y0, y1);
                }
            }
        }
    }
}

// ---------------- combine: out[t] = ybuf[2t] + ybuf[2t+1] (fp16 in, fp32 out) -------
__global__ void k_combine(float* __restrict__ out) {
    int i = blockIdx.x * blockDim.x + threadIdx.x;     // over T_*H_/8
    const int HW8 = H_ / 8;
    if (i < T_ * HW8) {
        int t = i / HW8, h8 = i % HW8;
        const uint4* yb = reinterpret_cast<const uint4*>(g_ybuf);
        uint4 a = yb[(size_t)(2 * t) * HW8 + h8];
        uint4 b = yb[(size_t)(2 * t + 1) * HW8 + h8];
        float4 o0, o1;
        {
            float2 p = __half22float2(*reinterpret_cast<__half2*>(&a.x));
            float2 q = __half22float2(*reinterpret_cast<__half2*>(&b.x));
            o0.x = p.x + q.x; o0.y = p.y + q.y;
            p = __half22float2(*reinterpret_cast<__half2*>(&a.y));
            q = __half22float2(*reinterpret_cast<__half2*>(&b.y));
            o0.z = p.x + q.x; o0.w = p.y + q.y;
            p = __half22float2(*reinterpret_cast<__half2*>(&a.z));
            q = __half22float2(*reinterpret_cast<__half2*>(&b.z));
            o1.x = p.x + q.x; o1.y = p.y + q.y;
            p = __half22float2(*reinterpret_cast<__half2*>(&a.w));
            q = __half22float2(*reinterpret_cast<__half2*>(&b.w));
            o1.z = p.x + q.x; o1.w = p.y + q.y;
        }
        float4* op = reinterpret_cast<float4*>(out + (size_t)t * H_ + h8 * 8);
        op[0] = o0; op[1] = o1;
    }
}

// ---------------- launch ----------------
extern "C" void kernel_launch(void* const* d_in, const int* in_sizes, int n_in,
                              void* d_out, int out_size) {
    const float* x   = (const float*)d_in[0];
    const float* w13 = (const float*)d_in[1];
    const float* w2  = (const float*)d_in[2];
    const float* tw  = (const float*)d_in[3];
    const void*  ids = d_in[4];
    float* out = (float*)d_out;

    const int smem = STAGES * STAGE_B;        // 98304 B per CTA
    cudaFuncSetAttribute(k_gemm13, cudaFuncAttributeMaxDynamicSharedMemorySize, smem);
    cudaFuncSetAttribute(k_gemm2,  cudaFuncAttributeMaxDynamicSharedMemorySize, smem);

    // idx 0: routing (block 0) + x/w13 fp16 convert (blocks 1..), MLP=2 loop
    k_prep<<<2961, 256>>>(ids, (const float4*)x, (const float4*)w13);
    // idx 1: gemm13 (z = 0..7) + w2 convert slice (z = 8), co-scheduled
    dim3 g13(I_ / 64, TK_ / 128, E_ + 1);     // (44, 64, 9)
    k_gemm13<<<g13, 256, smem>>>((const float4*)w2);
    // idx 2: gemm2
    dim3 g2(H_ / 128, TK_ / 128, E_);         // (16, 64, 8)
    k_gemm2<<<g2, 256, smem>>>(tw);
    // idx 3: combine
    k_combine<<<(T_ * (H_ / 8) + 255) / 256, 256>>>(out);
}